// round 8
// baseline (speedup 1.0000x reference)
#include <cuda_runtime.h>
#include <math.h>
#include <cstdint>

#define NN 4096
#define DD 64
#define HH 4
#define NSTEPS 4
#define NW (NN/32)   // 128 mask words per row

// ---------------- scratch (__device__ globals; no allocations) ----------------
__device__ float    g_h   [(size_t)HH * NN * DD];   // projected features per head
__device__ float    g_hn  [(size_t)HH * NN * DD];   // row-normalized
__device__ float    g_sim [(size_t)HH * NN * NN];   // 268 MB sim scratch
__device__ unsigned g_rowmax[HH * NN];              // ordered-int encoded masked row max
__device__ float    g_hmean [HH * DD];              // per-head column mean of h (fallback)
__device__ float    g_xbuf[2][NN * DD];             // feature ping-pong
__device__ unsigned g_adjbits[(size_t)NSTEPS * NN * NW]; // packed adjacency bits

// ordered-int encoding for float atomicMax
__device__ __forceinline__ unsigned f2ord(float f) {
    unsigned u = __float_as_uint(f);
    return (u & 0x80000000u) ? ~u : (u | 0x80000000u);
}
__device__ __forceinline__ float ord2f(unsigned u) {
    u = (u & 0x80000000u) ? (u & 0x7FFFFFFFu) : ~u;
    return __uint_as_float(u);
}
#define ORD_NEG_INF 0x007FFFFFu   // f2ord(-inf)

// ---------------- pack adjacency bits (all steps, once per launch) ----------------
__global__ void k_pack(const int* __restrict__ adj) {
    int lane = threadIdx.x & 31;
    size_t gw = (size_t)blockIdx.x * (blockDim.x >> 5) + (threadIdx.x >> 5);
    size_t nWtot = (size_t)NSTEPS * NN * NW;
    size_t stride = (size_t)gridDim.x * (blockDim.x >> 5);
    for (size_t w = gw; w < nWtot; w += stride) {
        int v = adj[w * 32 + lane];
        unsigned m = __ballot_sync(0xffffffffu, v > 0);
        if (lane == 0) g_adjbits[w] = m;
    }
}

// ---------------- per-step init: zero next-x, hmean, reset rowmax ----------------
__global__ void k_init(int step, float* dout) {
    float* nxt = (step == NSTEPS - 1) ? dout : g_xbuf[step & 1];
    int i = blockIdx.x * blockDim.x + threadIdx.x;
    if (i < NN * DD) nxt[i] = 0.f;
    if (i < HH * NN) g_rowmax[i] = ORD_NEG_INF;
    if (i < HH * DD) g_hmean[i] = 0.f;
}

// ---------------- projection + row-normalize + column mean (verbatim R1) ----------------
__global__ void k_project(int step, const float* __restrict__ feat,
                          const float* __restrict__ Ws) {
    const float* x = (step == 0) ? feat : g_xbuf[(step + 1) & 1];
    int h = blockIdx.y;
    const float* W = Ws + ((size_t)step * HH + h) * DD * DD;
    int row0 = blockIdx.x * 64;

    __shared__ float sW[DD * DD];
    __shared__ float sX[64 * DD];
    __shared__ float sPart[8][16];

    for (int i = threadIdx.x; i < DD * DD; i += 256) sW[i] = W[i];
    for (int i = threadIdx.x; i < 64 * DD; i += 256) sX[i] = x[(size_t)row0 * DD + i];
    __syncthreads();

    int tx = threadIdx.x & 63;
    int ty = threadIdx.x >> 6;

    float hv[16];
    #pragma unroll
    for (int i = 0; i < 16; i++) {
        int r = ty + i * 4;
        float acc = 0.f;
        #pragma unroll
        for (int d = 0; d < DD; d++) acc = fmaf(sX[r * DD + d], sW[d * DD + tx], acc);
        hv[i] = acc;
    }

    float ss[16];
    #pragma unroll
    for (int i = 0; i < 16; i++) ss[i] = hv[i] * hv[i];
    #pragma unroll
    for (int o = 16; o > 0; o >>= 1) {
        #pragma unroll
        for (int i = 0; i < 16; i++) ss[i] += __shfl_xor_sync(0xffffffffu, ss[i], o);
    }
    int w = threadIdx.x >> 5;
    if ((threadIdx.x & 31) == 0) {
        #pragma unroll
        for (int i = 0; i < 16; i++) sPart[w][i] = ss[i];
    }
    __syncthreads();

    float msum = 0.f;
    #pragma unroll
    for (int i = 0; i < 16; i++) {
        int r = ty + i * 4;
        float nsq = sPart[ty * 2][i] + sPart[ty * 2 + 1][i];
        float rn = 1.f / (sqrtf(nsq) + 1e-12f);
        size_t idx = ((size_t)h * NN + row0 + r) * DD + tx;
        g_h[idx]  = hv[i];
        g_hn[idx] = hv[i] * rn;
        msum += hv[i];
    }
    atomicAdd(&g_hmean[h * DD + tx], msum * (1.0f / NN));
}

// ---------------- sim = hn @ hn^T / TEMP ; store + masked row max (verbatim R1) ----------------
__global__ void k_sim(int step, const int* __restrict__ adjf) {
    extern __shared__ float sm[];
    float* sA = sm;               // [64][128] k-major
    float* sB = sm + 64 * 128;    // [64][128] k-major
    const int* adj = adjf + (size_t)step * NN * NN;
    int h  = blockIdx.z;
    int rb = blockIdx.y * 128, cb = blockIdx.x * 128;
    const float* base = g_hn + (size_t)h * NN * DD;

    #pragma unroll
    for (int t = 0; t < 8; t++) {
        int idx = threadIdx.x + t * 256;
        int r = idx >> 4;
        int k = (idx & 15) << 2;
        float4 va = *(const float4*)&base[(size_t)(rb + r) * DD + k];
        sA[(k + 0) * 128 + r] = va.x; sA[(k + 1) * 128 + r] = va.y;
        sA[(k + 2) * 128 + r] = va.z; sA[(k + 3) * 128 + r] = va.w;
        float4 vb = *(const float4*)&base[(size_t)(cb + r) * DD + k];
        sB[(k + 0) * 128 + r] = vb.x; sB[(k + 1) * 128 + r] = vb.y;
        sB[(k + 2) * 128 + r] = vb.z; sB[(k + 3) * 128 + r] = vb.w;
    }
    __syncthreads();

    int tx = threadIdx.x & 15, ty = threadIdx.x >> 4;
    float acc[8][8];
    #pragma unroll
    for (int i = 0; i < 8; i++)
        #pragma unroll
        for (int j = 0; j < 8; j++) acc[i][j] = 0.f;

    #pragma unroll
    for (int k = 0; k < 64; k++) {
        float4 a0 = *(const float4*)&sA[k * 128 + ty * 4];
        float4 a1 = *(const float4*)&sA[k * 128 + ty * 4 + 64];
        float4 b0 = *(const float4*)&sB[k * 128 + tx * 4];
        float4 b1 = *(const float4*)&sB[k * 128 + tx * 4 + 64];
        float a[8] = {a0.x, a0.y, a0.z, a0.w, a1.x, a1.y, a1.z, a1.w};
        float b[8] = {b0.x, b0.y, b0.z, b0.w, b1.x, b1.y, b1.z, b1.w};
        #pragma unroll
        for (int i = 0; i < 8; i++)
            #pragma unroll
            for (int j = 0; j < 8; j++) acc[i][j] = fmaf(a[i], b[j], acc[i][j]);
    }

    float* simbase = g_sim + (size_t)h * NN * NN;
    float rmax[8];
    #pragma unroll
    for (int i = 0; i < 8; i++) rmax[i] = -INFINITY;

    #pragma unroll
    for (int i = 0; i < 8; i++) {
        int lr = ty * 4 + (i & 3) + ((i >> 2) << 6);
        int gr = rb + lr;
        float4 s0 = make_float4(acc[i][0] * 5.f, acc[i][1] * 5.f, acc[i][2] * 5.f, acc[i][3] * 5.f);
        float4 s1 = make_float4(acc[i][4] * 5.f, acc[i][5] * 5.f, acc[i][6] * 5.f, acc[i][7] * 5.f);
        size_t o0 = (size_t)gr * NN + cb + tx * 4;
        *(float4*)&simbase[o0]      = s0;
        *(float4*)&simbase[o0 + 64] = s1;
        int4 m0 = *(const int4*)&adj[o0];
        int4 m1 = *(const int4*)&adj[o0 + 64];
        if (m0.x > 0) rmax[i] = fmaxf(rmax[i], s0.x);
        if (m0.y > 0) rmax[i] = fmaxf(rmax[i], s0.y);
        if (m0.z > 0) rmax[i] = fmaxf(rmax[i], s0.z);
        if (m0.w > 0) rmax[i] = fmaxf(rmax[i], s0.w);
        if (m1.x > 0) rmax[i] = fmaxf(rmax[i], s1.x);
        if (m1.y > 0) rmax[i] = fmaxf(rmax[i], s1.y);
        if (m1.z > 0) rmax[i] = fmaxf(rmax[i], s1.z);
        if (m1.w > 0) rmax[i] = fmaxf(rmax[i], s1.w);
    }

    __syncthreads();
    unsigned* smax = (unsigned*)sA;
    if (threadIdx.x < 128) smax[threadIdx.x] = ORD_NEG_INF;
    __syncthreads();
    #pragma unroll
    for (int i = 0; i < 8; i++) {
        int lr = ty * 4 + (i & 3) + ((i >> 2) << 6);
        atomicMax(&smax[lr], f2ord(rmax[i]));
    }
    __syncthreads();
    if (threadIdx.x < 128)
        atomicMax(&g_rowmax[h * NN + rb + threadIdx.x], smax[threadIdx.x]);
}

// ---------------- keep + exp + P@h + elu + head mean ----------------
// grid (NN/128, HH). block 256. Tile 128 rows x 64 cols, 8x4 micro-tile.
#define SP_STRIDE 132
#define ATTN_SMEM ((128 * SP_STRIDE + 128 * 64 + 128 + 128) * 4)
__global__ void __launch_bounds__(256, 1) k_attn(int step, float* __restrict__ doutp) {
    extern __shared__ float sm[];
    float* sP   = sm;                       // [128][SP_STRIDE]
    float* sHt  = sm + 128 * SP_STRIDE;     // [128][64]
    float* sRM  = sHt + 128 * 64;           // [128]
    float* sDen = sRM + 128;                // [128]

    float* out = (step == NSTEPS - 1) ? doutp : g_xbuf[step & 1];
    int h = blockIdx.y;
    int rb = blockIdx.x * 128;
    int tid = threadIdx.x;
    int warp = tid >> 5, lane = tid & 31;

    if (tid < 128) {
        sRM[tid] = ord2f(g_rowmax[h * NN + rb + tid]);
        sDen[tid] = 0.f;
    }
    __syncthreads();

    int tx = tid & 15, ty = tid >> 4;       // cols tx*4..+3, rows ty*8..+7
    float acc[8][4];
    #pragma unroll
    for (int i = 0; i < 8; i++)
        #pragma unroll
        for (int j = 0; j < 4; j++) acc[i][j] = 0.f;

    const float* hb = g_h + (size_t)h * NN * DD;
    const float* simb = g_sim + (size_t)h * NN * NN;
    const unsigned* adjb = g_adjbits + (size_t)step * NN * NW;

    for (int cb = 0; cb < NN; cb += 128) {
        __syncthreads();
        // p-phase: one row per warp-iteration (128 cols); unrolled -> high MLP
        #pragma unroll
        for (int t = 0; t < 16; t++) {
            int r = t * 8 + warp;
            int gr = rb + r;
            float rm = sRM[r];
            float th = 0.5f * rm;
            float4 s = *(const float4*)&simb[(size_t)gr * NN + cb + lane * 4];
            unsigned mb = adjb[(size_t)gr * NW + (cb >> 5) + (lane >> 3)];
            int b0 = (lane & 7) * 4;
            float4 p;
            p.x = (((mb >> (b0 + 0)) & 1) && s.x >= th) ? __expf(s.x - rm) : 0.f;
            p.y = (((mb >> (b0 + 1)) & 1) && s.y >= th) ? __expf(s.y - rm) : 0.f;
            p.z = (((mb >> (b0 + 2)) & 1) && s.z >= th) ? __expf(s.z - rm) : 0.f;
            p.w = (((mb >> (b0 + 3)) & 1) && s.w >= th) ? __expf(s.w - rm) : 0.f;
            *(float4*)&sP[r * SP_STRIDE + lane * 4] = p;
            float ws = p.x + p.y + p.z + p.w;
            #pragma unroll
            for (int o = 16; o > 0; o >>= 1) ws += __shfl_xor_sync(0xffffffffu, ws, o);
            if (lane == 0) sDen[r] += ws;
        }
        // h col-tile [128][64]
        #pragma unroll
        for (int t = 0; t < 8; t++) {
            int idx = tid + t * 256;
            int cc = idx >> 4, e = (idx & 15) << 2;
            *(float4*)&sHt[cc * 64 + e] = *(const float4*)&hb[(size_t)(cb + cc) * DD + e];
        }
        __syncthreads();
        // GEMM: 8 rows x 4 cols per thread, k unrolled by 4 with float4 P loads
        #pragma unroll 1
        for (int k = 0; k < 128; k += 4) {
            float4 a[8];
            #pragma unroll
            for (int i = 0; i < 8; i++)
                a[i] = *(const float4*)&sP[(ty * 8 + i) * SP_STRIDE + k];
            #pragma unroll
            for (int kk = 0; kk < 4; kk++) {
                float4 b = *(const float4*)&sHt[(k + kk) * 64 + tx * 4];
                #pragma unroll
                for (int i = 0; i < 8; i++) {
                    float av = (kk == 0) ? a[i].x : (kk == 1) ? a[i].y : (kk == 2) ? a[i].z : a[i].w;
                    acc[i][0] = fmaf(av, b.x, acc[i][0]);
                    acc[i][1] = fmaf(av, b.y, acc[i][1]);
                    acc[i][2] = fmaf(av, b.z, acc[i][2]);
                    acc[i][3] = fmaf(av, b.w, acc[i][3]);
                }
            }
        }
    }
    __syncthreads();

    #pragma unroll
    for (int i = 0; i < 8; i++) {
        int lr = ty * 8 + i;
        int r = rb + lr;
        float den = sDen[lr];
        float inv = (den > 0.f) ? (1.f / den) : 0.f;
        #pragma unroll
        for (int j = 0; j < 4; j++) {
            int e = tx * 4 + j;
            float v = (den > 0.f) ? (acc[i][j] * inv) : g_hmean[h * DD + e];
            v = (v > 0.f) ? v : (expf(v) - 1.f);   // elu
            atomicAdd(&out[(size_t)r * DD + e], 0.25f * v);
        }
    }
}

// ---------------- launch ----------------
extern "C" void kernel_launch(void* const* d_in, const int* in_sizes, int n_in,
                              void* d_out, int out_size) {
    const float* feat = (const float*)d_in[0];
    const int*   adj  = (const int*)d_in[1];
    const float* Ws   = (const float*)d_in[2];
    float* out = (float*)d_out;

    const int simSmem = 64 * 128 * 2 * (int)sizeof(float);   // 64 KB
    cudaFuncSetAttribute(k_sim,  cudaFuncAttributeMaxDynamicSharedMemorySize, simSmem);
    cudaFuncSetAttribute(k_attn, cudaFuncAttributeMaxDynamicSharedMemorySize, ATTN_SMEM);

    k_pack<<<2048, 256>>>(adj);
    for (int s = 0; s < NSTEPS; s++) {
        k_init<<<1024, 256>>>(s, out);
        k_project<<<dim3(NN / 64, HH), 256>>>(s, feat, Ws);
        k_sim<<<dim3(NN / 128, NN / 128, HH), 256, simSmem>>>(s, adj);
        k_attn<<<dim3(NN / 128, HH), 256, ATTN_SMEM>>>(s, out);
    }
}

// round 9
// speedup vs baseline: 1.0323x; 1.0323x over previous
#include <cuda_runtime.h>
#include <math.h>
#include <cstdint>

#define NN 4096
#define DD 64
#define HH 4
#define NSTEPS 4
#define NW (NN/32)   // 128 mask words per row

// ---------------- scratch (__device__ globals; no allocations) ----------------
__device__ float    g_h   [(size_t)HH * NN * DD];
__device__ float    g_hn  [(size_t)HH * NN * DD];
__device__ float    g_sim [(size_t)HH * NN * NN];   // 268 MB sim scratch
__device__ unsigned g_rowmax[HH * NN];
__device__ float    g_hmean [HH * DD];
__device__ float    g_xbuf[2][NN * DD];
__device__ unsigned g_adjbits[(size_t)NSTEPS * NN * NW];

__device__ __forceinline__ unsigned f2ord(float f) {
    unsigned u = __float_as_uint(f);
    return (u & 0x80000000u) ? ~u : (u | 0x80000000u);
}
__device__ __forceinline__ float ord2f(unsigned u) {
    u = (u & 0x80000000u) ? (u & 0x7FFFFFFFu) : ~u;
    return __uint_as_float(u);
}
#define ORD_NEG_INF 0x007FFFFFu

// ---------------- pack adjacency bits (all steps, once) ----------------
__global__ void k_pack(const int* __restrict__ adj) {
    int lane = threadIdx.x & 31;
    size_t gw = (size_t)blockIdx.x * (blockDim.x >> 5) + (threadIdx.x >> 5);
    size_t nWtot = (size_t)NSTEPS * NN * NW;
    size_t stride = (size_t)gridDim.x * (blockDim.x >> 5);
    for (size_t w = gw; w < nWtot; w += stride) {
        int v = adj[w * 32 + lane];
        unsigned m = __ballot_sync(0xffffffffu, v > 0);
        if (lane == 0) g_adjbits[w] = m;
    }
}

// ---------------- per-step init ----------------
__global__ void k_init(int step, float* dout) {
    float* nxt = (step == NSTEPS - 1) ? dout : g_xbuf[step & 1];
    int i = blockIdx.x * blockDim.x + threadIdx.x;
    if (i < NN * DD) nxt[i] = 0.f;
    if (i < HH * NN) g_rowmax[i] = ORD_NEG_INF;
    if (i < HH * DD) g_hmean[i] = 0.f;
}

// ---------------- projection + row-normalize + column mean (verbatim R1) ----------------
__global__ void k_project(int step, const float* __restrict__ feat,
                          const float* __restrict__ Ws) {
    const float* x = (step == 0) ? feat : g_xbuf[(step + 1) & 1];
    int h = blockIdx.y;
    const float* W = Ws + ((size_t)step * HH + h) * DD * DD;
    int row0 = blockIdx.x * 64;

    __shared__ float sW[DD * DD];
    __shared__ float sX[64 * DD];
    __shared__ float sPart[8][16];

    for (int i = threadIdx.x; i < DD * DD; i += 256) sW[i] = W[i];
    for (int i = threadIdx.x; i < 64 * DD; i += 256) sX[i] = x[(size_t)row0 * DD + i];
    __syncthreads();

    int tx = threadIdx.x & 63;
    int ty = threadIdx.x >> 6;

    float hv[16];
    #pragma unroll
    for (int i = 0; i < 16; i++) {
        int r = ty + i * 4;
        float acc = 0.f;
        #pragma unroll
        for (int d = 0; d < DD; d++) acc = fmaf(sX[r * DD + d], sW[d * DD + tx], acc);
        hv[i] = acc;
    }

    float ss[16];
    #pragma unroll
    for (int i = 0; i < 16; i++) ss[i] = hv[i] * hv[i];
    #pragma unroll
    for (int o = 16; o > 0; o >>= 1) {
        #pragma unroll
        for (int i = 0; i < 16; i++) ss[i] += __shfl_xor_sync(0xffffffffu, ss[i], o);
    }
    int w = threadIdx.x >> 5;
    if ((threadIdx.x & 31) == 0) {
        #pragma unroll
        for (int i = 0; i < 16; i++) sPart[w][i] = ss[i];
    }
    __syncthreads();

    float msum = 0.f;
    #pragma unroll
    for (int i = 0; i < 16; i++) {
        int r = ty + i * 4;
        float nsq = sPart[ty * 2][i] + sPart[ty * 2 + 1][i];
        float rn = 1.f / (sqrtf(nsq) + 1e-12f);
        size_t idx = ((size_t)h * NN + row0 + r) * DD + tx;
        g_h[idx]  = hv[i];
        g_hn[idx] = hv[i] * rn;
        msum += hv[i];
    }
    atomicAdd(&g_hmean[h * DD + tx], msum * (1.0f / NN));
}

// ---------------- sim = hn @ hn^T / TEMP, symmetric: upper tiles only ----------------
// grid (528, HH): upper-triangular 128x128 tile pairs. block 256 (16x16, 8x8 micro).
// smem: GEMM phase sA/sB [64][128] each (64KB); epilogue overlays sT[128][129] (64.5KB).
#define SIM_SMEM (128 * 129 * 4)
__global__ void __launch_bounds__(256) k_sim(int step) {
    extern __shared__ float sm[];
    float* sA = sm;               // [64][128] k-major
    float* sB = sm + 64 * 128;    // [64][128] k-major
    int h = blockIdx.y;

    // map blockIdx.x -> (bi, bj), bi <= bj, 32 tiles per dim
    int idx = blockIdx.x, bi = 0;
    while (idx >= 32 - bi) { idx -= 32 - bi; bi++; }
    int bj = bi + idx;
    int rb = bi * 128, cb = bj * 128;

    const float* base = g_hn + (size_t)h * NN * DD;
    #pragma unroll
    for (int t = 0; t < 8; t++) {
        int i2 = threadIdx.x + t * 256;
        int r = i2 >> 4;
        int k = (i2 & 15) << 2;
        float4 va = *(const float4*)&base[(size_t)(rb + r) * DD + k];
        sA[(k + 0) * 128 + r] = va.x; sA[(k + 1) * 128 + r] = va.y;
        sA[(k + 2) * 128 + r] = va.z; sA[(k + 3) * 128 + r] = va.w;
        float4 vb = *(const float4*)&base[(size_t)(cb + r) * DD + k];
        sB[(k + 0) * 128 + r] = vb.x; sB[(k + 1) * 128 + r] = vb.y;
        sB[(k + 2) * 128 + r] = vb.z; sB[(k + 3) * 128 + r] = vb.w;
    }
    __syncthreads();

    int tx = threadIdx.x & 15, ty = threadIdx.x >> 4;
    float acc[8][8];
    #pragma unroll
    for (int i = 0; i < 8; i++)
        #pragma unroll
        for (int j = 0; j < 8; j++) acc[i][j] = 0.f;

    #pragma unroll
    for (int k = 0; k < 64; k++) {
        float4 a0 = *(const float4*)&sA[k * 128 + ty * 4];
        float4 a1 = *(const float4*)&sA[k * 128 + ty * 4 + 64];
        float4 b0 = *(const float4*)&sB[k * 128 + tx * 4];
        float4 b1 = *(const float4*)&sB[k * 128 + tx * 4 + 64];
        float a[8] = {a0.x, a0.y, a0.z, a0.w, a1.x, a1.y, a1.z, a1.w};
        float b[8] = {b0.x, b0.y, b0.z, b0.w, b1.x, b1.y, b1.z, b1.w};
        #pragma unroll
        for (int i = 0; i < 8; i++)
            #pragma unroll
            for (int j = 0; j < 8; j++) acc[i][j] = fmaf(a[i], b[j], acc[i][j]);
    }

    // scale by 1/TEMP = 5 in place
    #pragma unroll
    for (int i = 0; i < 8; i++)
        #pragma unroll
        for (int j = 0; j < 8; j++) acc[i][j] *= 5.f;

    // row-side store + masked row max via adjbits
    const unsigned* bits = g_adjbits + (size_t)step * NN * NW;
    float* simbase = g_sim + (size_t)h * NN * NN;
    int lane = threadIdx.x & 31;
    #pragma unroll
    for (int i = 0; i < 8; i++) {
        int lr = ty * 4 + (i & 3) + ((i >> 2) << 6);
        int gr = rb + lr;
        size_t o0 = (size_t)gr * NN + cb + tx * 4;
        *(float4*)&simbase[o0]      = make_float4(acc[i][0], acc[i][1], acc[i][2], acc[i][3]);
        *(float4*)&simbase[o0 + 64] = make_float4(acc[i][4], acc[i][5], acc[i][6], acc[i][7]);
        unsigned w0 = bits[(size_t)gr * NW + (cb >> 5) + (tx >> 3)];
        unsigned w1 = bits[(size_t)gr * NW + (cb >> 5) + 2 + (tx >> 3)];
        int bo = (tx & 7) * 4;
        float lm = -INFINITY;
        #pragma unroll
        for (int j = 0; j < 4; j++) {
            if ((w0 >> (bo + j)) & 1) lm = fmaxf(lm, acc[i][j]);
            if ((w1 >> (bo + j)) & 1) lm = fmaxf(lm, acc[i][4 + j]);
        }
        // reduce over the 16 tx lanes sharing this row (lanes 0-15 / 16-31 halves)
        lm = fmaxf(lm, __shfl_xor_sync(0xffffffffu, lm, 1));
        lm = fmaxf(lm, __shfl_xor_sync(0xffffffffu, lm, 2));
        lm = fmaxf(lm, __shfl_xor_sync(0xffffffffu, lm, 4));
        lm = fmaxf(lm, __shfl_xor_sync(0xffffffffu, lm, 8));
        if ((lane & 15) == 0) atomicMax(&g_rowmax[h * NN + gr], f2ord(lm));
    }

    // mirror tile: transpose via smem, coalesced store + mirror row max
    if (bi != bj) {
        __syncthreads();                 // all GEMM smem reads done
        float* sT = sm;                  // [128][129]
        #pragma unroll
        for (int i = 0; i < 8; i++) {
            int lr = ty * 4 + (i & 3) + ((i >> 2) << 6);
            #pragma unroll
            for (int j = 0; j < 8; j++) {
                int c = tx * 4 + (j & 3) + ((j >> 2) << 6);
                sT[c * 129 + lr] = acc[i][j];
            }
        }
        __syncthreads();
        #pragma unroll
        for (int t = 0; t < 16; t++) {
            int slot = threadIdx.x + t * 256;   // 0..4095
            int c = slot >> 5;                  // mirror row 0..127
            int s = slot & 31;                  // float4 col slot
            int gr = cb + c;
            float4 v = make_float4(sT[c * 129 + s * 4 + 0], sT[c * 129 + s * 4 + 1],
                                   sT[c * 129 + s * 4 + 2], sT[c * 129 + s * 4 + 3]);
            *(float4*)&simbase[(size_t)gr * NN + rb + s * 4] = v;
            unsigned w = bits[(size_t)gr * NW + (rb >> 5) + (s >> 3)];
            int bo = (s & 7) * 4;
            float lm = -INFINITY;
            if ((w >> (bo + 0)) & 1) lm = fmaxf(lm, v.x);
            if ((w >> (bo + 1)) & 1) lm = fmaxf(lm, v.y);
            if ((w >> (bo + 2)) & 1) lm = fmaxf(lm, v.z);
            if ((w >> (bo + 3)) & 1) lm = fmaxf(lm, v.w);
            #pragma unroll
            for (int o = 16; o > 0; o >>= 1)
                lm = fmaxf(lm, __shfl_xor_sync(0xffffffffu, lm, o));
            if (lane == 0) atomicMax(&g_rowmax[h * NN + gr], f2ord(lm));
        }
    }
}

// ---------------- keep + exp + P@h + elu + head mean ----------------
// grid (NN/32, HH). block 256. Tile 32 rows x 64 cols; rows on lanes (ty=tid&15).
#define SP_STRIDE 132
#define ATTN_SMEM ((32 * SP_STRIDE + 128 * 64 + 32 + 32) * 4)
__global__ void __launch_bounds__(256) k_attn(int step, float* __restrict__ doutp) {
    extern __shared__ float sm[];
    float* sP   = sm;                      // [32][SP_STRIDE]
    float* sHt  = sm + 32 * SP_STRIDE;     // [128][64]
    float* sRM  = sHt + 128 * 64;          // [32]
    float* sDen = sRM + 32;                // [32]

    float* out = (step == NSTEPS - 1) ? doutp : g_xbuf[step & 1];
    int h = blockIdx.y;
    int rb = blockIdx.x * 32;
    int tid = threadIdx.x;
    int warp = tid >> 5, lane = tid & 31;

    if (tid < 32) {
        sRM[tid] = ord2f(g_rowmax[h * NN + rb + tid]);
        sDen[tid] = 0.f;
    }

    int ty = tid & 15, tx = tid >> 4;      // rows ty*2+i, cols tx*4+j
    float acc[2][4];
    #pragma unroll
    for (int i = 0; i < 2; i++)
        #pragma unroll
        for (int j = 0; j < 4; j++) acc[i][j] = 0.f;

    const float* hb = g_h + (size_t)h * NN * DD;
    const float* simb = g_sim + (size_t)h * NN * NN;
    const unsigned* adjb = g_adjbits + (size_t)step * NN * NW;

    for (int cb = 0; cb < NN; cb += 128) {
        __syncthreads();
        // p-phase: warp handles one row (128 cols) per iteration; 4 iters
        #pragma unroll
        for (int t = 0; t < 4; t++) {
            int r = t * 8 + warp;
            int gr = rb + r;
            float rm = sRM[r];
            float th = 0.5f * rm;
            float4 s = *(const float4*)&simb[(size_t)gr * NN + cb + lane * 4];
            unsigned mb = adjb[(size_t)gr * NW + (cb >> 5) + (lane >> 3)];
            int b0 = (lane & 7) * 4;
            float4 p;
            p.x = (((mb >> (b0 + 0)) & 1) && s.x >= th) ? __expf(s.x - rm) : 0.f;
            p.y = (((mb >> (b0 + 1)) & 1) && s.y >= th) ? __expf(s.y - rm) : 0.f;
            p.z = (((mb >> (b0 + 2)) & 1) && s.z >= th) ? __expf(s.z - rm) : 0.f;
            p.w = (((mb >> (b0 + 3)) & 1) && s.w >= th) ? __expf(s.w - rm) : 0.f;
            *(float4*)&sP[r * SP_STRIDE + lane * 4] = p;
            float ws = p.x + p.y + p.z + p.w;
            #pragma unroll
            for (int o = 16; o > 0; o >>= 1) ws += __shfl_xor_sync(0xffffffffu, ws, o);
            if (lane == 0) sDen[r] += ws;
        }
        // h col-tile [128][64]
        #pragma unroll
        for (int t = 0; t < 8; t++) {
            int i2 = tid + t * 256;
            int cc = i2 >> 4, e = (i2 & 15) << 2;
            *(float4*)&sHt[cc * 64 + e] = *(const float4*)&hb[(size_t)(cb + cc) * DD + e];
        }
        __syncthreads();
        // GEMM: 2 rows x 4 cols per thread, k unrolled by 4 (float4 A loads)
        #pragma unroll 2
        for (int k = 0; k < 128; k += 4) {
            float4 a0 = *(const float4*)&sP[(ty * 2 + 0) * SP_STRIDE + k];
            float4 a1 = *(const float4*)&sP[(ty * 2 + 1) * SP_STRIDE + k];
            #pragma unroll
            for (int kk = 0; kk < 4; kk++) {
                float4 b = *(const float4*)&sHt[(k + kk) * 64 + tx * 4];
                float av0 = (kk == 0) ? a0.x : (kk == 1) ? a0.y : (kk == 2) ? a0.z : a0.w;
                float av1 = (kk == 0) ? a1.x : (kk == 1) ? a1.y : (kk == 2) ? a1.z : a1.w;
                acc[0][0] = fmaf(av0, b.x, acc[0][0]);
                acc[0][1] = fmaf(av0, b.y, acc[0][1]);
                acc[0][2] = fmaf(av0, b.z, acc[0][2]);
                acc[0][3] = fmaf(av0, b.w, acc[0][3]);
                acc[1][0] = fmaf(av1, b.x, acc[1][0]);
                acc[1][1] = fmaf(av1, b.y, acc[1][1]);
                acc[1][2] = fmaf(av1, b.z, acc[1][2]);
                acc[1][3] = fmaf(av1, b.w, acc[1][3]);
            }
        }
    }
    __syncthreads();

    #pragma unroll
    for (int i = 0; i < 2; i++) {
        int lr = ty * 2 + i;
        int r = rb + lr;
        float den = sDen[lr];
        float inv = (den > 0.f) ? (1.f / den) : 0.f;
        #pragma unroll
        for (int j = 0; j < 4; j++) {
            int e = tx * 4 + j;
            float v = (den > 0.f) ? (acc[i][j] * inv) : g_hmean[h * DD + e];
            v = (v > 0.f) ? v : (expf(v) - 1.f);   // elu
            atomicAdd(&out[(size_t)r * DD + e], 0.25f * v);
        }
    }
}

// ---------------- launch ----------------
extern "C" void kernel_launch(void* const* d_in, const int* in_sizes, int n_in,
                              void* d_out, int out_size) {
    const float* feat = (const float*)d_in[0];
    const int*   adj  = (const int*)d_in[1];
    const float* Ws   = (const float*)d_in[2];
    float* out = (float*)d_out;

    cudaFuncSetAttribute(k_sim,  cudaFuncAttributeMaxDynamicSharedMemorySize, SIM_SMEM);
    cudaFuncSetAttribute(k_attn, cudaFuncAttributeMaxDynamicSharedMemorySize, ATTN_SMEM);

    k_pack<<<2048, 256>>>(adj);
    for (int s = 0; s < NSTEPS; s++) {
        k_init<<<1024, 256>>>(s, out);
        k_project<<<dim3(NN / 64, HH), 256>>>(s, feat, Ws);
        k_sim<<<dim3(528, HH), 256, SIM_SMEM>>>(s);
        k_attn<<<dim3(NN / 32, HH), 256, ATTN_SMEM>>>(s, out);
    }
}

// round 13
// speedup vs baseline: 1.1813x; 1.1443x over previous
#include <cuda_runtime.h>
#include <math.h>
#include <cstdint>

#define NN 4096
#define DD 64
#define HH 4
#define NSTEPS 4
#define NW (NN/32)   // 128 mask words per row

// ---------------- scratch (__device__ globals; no allocations) ----------------
__device__ float    g_h   [(size_t)HH * NN * DD];
__device__ float    g_hn  [(size_t)HH * NN * DD];
__device__ float    g_sim [(size_t)HH * NN * NN];   // 268 MB sim scratch
__device__ unsigned g_rowmax[HH * NN];
__device__ float    g_hmean [HH * DD];
__device__ float    g_xbuf[2][NN * DD];
__device__ unsigned g_adjbits[(size_t)NSTEPS * NN * NW];

__device__ __forceinline__ unsigned f2ord(float f) {
    unsigned u = __float_as_uint(f);
    return (u & 0x80000000u) ? ~u : (u | 0x80000000u);
}
__device__ __forceinline__ float ord2f(unsigned u) {
    u = (u & 0x80000000u) ? (u & 0x7FFFFFFFu) : ~u;
    return __uint_as_float(u);
}
#define ORD_NEG_INF 0x007FFFFFu

// ---------------- pack adjacency bits (all steps, once) ----------------
__global__ void k_pack(const int* __restrict__ adj) {
    int lane = threadIdx.x & 31;
    size_t gw = (size_t)blockIdx.x * (blockDim.x >> 5) + (threadIdx.x >> 5);
    size_t nWtot = (size_t)NSTEPS * NN * NW;
    size_t stride = (size_t)gridDim.x * (blockDim.x >> 5);
    for (size_t w = gw; w < nWtot; w += stride) {
        int v = adj[w * 32 + lane];
        unsigned m = __ballot_sync(0xffffffffu, v > 0);
        if (lane == 0) g_adjbits[w] = m;
    }
}

// ---------------- per-step init ----------------
__global__ void k_init(int step, float* dout) {
    float* nxt = (step == NSTEPS - 1) ? dout : g_xbuf[step & 1];
    int i = blockIdx.x * blockDim.x + threadIdx.x;
    if (i < NN * DD) nxt[i] = 0.f;
    if (i < HH * NN) g_rowmax[i] = ORD_NEG_INF;
    if (i < HH * DD) g_hmean[i] = 0.f;
}

// ---------------- projection + row-normalize + column mean (verbatim R1) ----------------
__global__ void k_project(int step, const float* __restrict__ feat,
                          const float* __restrict__ Ws) {
    const float* x = (step == 0) ? feat : g_xbuf[(step + 1) & 1];
    int h = blockIdx.y;
    const float* W = Ws + ((size_t)step * HH + h) * DD * DD;
    int row0 = blockIdx.x * 64;

    __shared__ float sW[DD * DD];
    __shared__ float sX[64 * DD];
    __shared__ float sPart[8][16];

    for (int i = threadIdx.x; i < DD * DD; i += 256) sW[i] = W[i];
    for (int i = threadIdx.x; i < 64 * DD; i += 256) sX[i] = x[(size_t)row0 * DD + i];
    __syncthreads();

    int tx = threadIdx.x & 63;
    int ty = threadIdx.x >> 6;

    float hv[16];
    #pragma unroll
    for (int i = 0; i < 16; i++) {
        int r = ty + i * 4;
        float acc = 0.f;
        #pragma unroll
        for (int d = 0; d < DD; d++) acc = fmaf(sX[r * DD + d], sW[d * DD + tx], acc);
        hv[i] = acc;
    }

    float ss[16];
    #pragma unroll
    for (int i = 0; i < 16; i++) ss[i] = hv[i] * hv[i];
    #pragma unroll
    for (int o = 16; o > 0; o >>= 1) {
        #pragma unroll
        for (int i = 0; i < 16; i++) ss[i] += __shfl_xor_sync(0xffffffffu, ss[i], o);
    }
    int w = threadIdx.x >> 5;
    if ((threadIdx.x & 31) == 0) {
        #pragma unroll
        for (int i = 0; i < 16; i++) sPart[w][i] = ss[i];
    }
    __syncthreads();

    float msum = 0.f;
    #pragma unroll
    for (int i = 0; i < 16; i++) {
        int r = ty + i * 4;
        float nsq = sPart[ty * 2][i] + sPart[ty * 2 + 1][i];
        float rn = 1.f / (sqrtf(nsq) + 1e-12f);
        size_t idx = ((size_t)h * NN + row0 + r) * DD + tx;
        g_h[idx]  = hv[i];
        g_hn[idx] = hv[i] * rn;
        msum += hv[i];
    }
    atomicAdd(&g_hmean[h * DD + tx], msum * (1.0f / NN));
}

// ---------------- sim = hn @ hn^T / TEMP, symmetric: upper tiles only (verbatim R9) ----------------
#define SIM_SMEM (128 * 129 * 4)
__global__ void __launch_bounds__(256) k_sim(int step) {
    extern __shared__ float sm[];
    float* sA = sm;               // [64][128] k-major
    float* sB = sm + 64 * 128;    // [64][128] k-major
    int h = blockIdx.y;

    int idx = blockIdx.x, bi = 0;
    while (idx >= 32 - bi) { idx -= 32 - bi; bi++; }
    int bj = bi + idx;
    int rb = bi * 128, cb = bj * 128;

    const float* base = g_hn + (size_t)h * NN * DD;
    #pragma unroll
    for (int t = 0; t < 8; t++) {
        int i2 = threadIdx.x + t * 256;
        int r = i2 >> 4;
        int k = (i2 & 15) << 2;
        float4 va = *(const float4*)&base[(size_t)(rb + r) * DD + k];
        sA[(k + 0) * 128 + r] = va.x; sA[(k + 1) * 128 + r] = va.y;
        sA[(k + 2) * 128 + r] = va.z; sA[(k + 3) * 128 + r] = va.w;
        float4 vb = *(const float4*)&base[(size_t)(cb + r) * DD + k];
        sB[(k + 0) * 128 + r] = vb.x; sB[(k + 1) * 128 + r] = vb.y;
        sB[(k + 2) * 128 + r] = vb.z; sB[(k + 3) * 128 + r] = vb.w;
    }
    __syncthreads();

    int tx = threadIdx.x & 15, ty = threadIdx.x >> 4;
    float acc[8][8];
    #pragma unroll
    for (int i = 0; i < 8; i++)
        #pragma unroll
        for (int j = 0; j < 8; j++) acc[i][j] = 0.f;

    #pragma unroll
    for (int k = 0; k < 64; k++) {
        float4 a0 = *(const float4*)&sA[k * 128 + ty * 4];
        float4 a1 = *(const float4*)&sA[k * 128 + ty * 4 + 64];
        float4 b0 = *(const float4*)&sB[k * 128 + tx * 4];
        float4 b1 = *(const float4*)&sB[k * 128 + tx * 4 + 64];
        float a[8] = {a0.x, a0.y, a0.z, a0.w, a1.x, a1.y, a1.z, a1.w};
        float b[8] = {b0.x, b0.y, b0.z, b0.w, b1.x, b1.y, b1.z, b1.w};
        #pragma unroll
        for (int i = 0; i < 8; i++)
            #pragma unroll
            for (int j = 0; j < 8; j++) acc[i][j] = fmaf(a[i], b[j], acc[i][j]);
    }

    #pragma unroll
    for (int i = 0; i < 8; i++)
        #pragma unroll
        for (int j = 0; j < 8; j++) acc[i][j] *= 5.f;

    const unsigned* bits = g_adjbits + (size_t)step * NN * NW;
    float* simbase = g_sim + (size_t)h * NN * NN;
    int lane = threadIdx.x & 31;
    #pragma unroll
    for (int i = 0; i < 8; i++) {
        int lr = ty * 4 + (i & 3) + ((i >> 2) << 6);
        int gr = rb + lr;
        size_t o0 = (size_t)gr * NN + cb + tx * 4;
        *(float4*)&simbase[o0]      = make_float4(acc[i][0], acc[i][1], acc[i][2], acc[i][3]);
        *(float4*)&simbase[o0 + 64] = make_float4(acc[i][4], acc[i][5], acc[i][6], acc[i][7]);
        unsigned w0 = bits[(size_t)gr * NW + (cb >> 5) + (tx >> 3)];
        unsigned w1 = bits[(size_t)gr * NW + (cb >> 5) + 2 + (tx >> 3)];
        int bo = (tx & 7) * 4;
        float lm = -INFINITY;
        #pragma unroll
        for (int j = 0; j < 4; j++) {
            if ((w0 >> (bo + j)) & 1) lm = fmaxf(lm, acc[i][j]);
            if ((w1 >> (bo + j)) & 1) lm = fmaxf(lm, acc[i][4 + j]);
        }
        lm = fmaxf(lm, __shfl_xor_sync(0xffffffffu, lm, 1));
        lm = fmaxf(lm, __shfl_xor_sync(0xffffffffu, lm, 2));
        lm = fmaxf(lm, __shfl_xor_sync(0xffffffffu, lm, 4));
        lm = fmaxf(lm, __shfl_xor_sync(0xffffffffu, lm, 8));
        if ((lane & 15) == 0) atomicMax(&g_rowmax[h * NN + gr], f2ord(lm));
    }

    if (bi != bj) {
        __syncthreads();
        float* sT = sm;                  // [128][129]
        #pragma unroll
        for (int i = 0; i < 8; i++) {
            int lr = ty * 4 + (i & 3) + ((i >> 2) << 6);
            #pragma unroll
            for (int j = 0; j < 8; j++) {
                int c = tx * 4 + (j & 3) + ((j >> 2) << 6);
                sT[c * 129 + lr] = acc[i][j];
            }
        }
        __syncthreads();
        #pragma unroll
        for (int t = 0; t < 16; t++) {
            int slot = threadIdx.x + t * 256;
            int c = slot >> 5;
            int s = slot & 31;
            int gr = cb + c;
            float4 v = make_float4(sT[c * 129 + s * 4 + 0], sT[c * 129 + s * 4 + 1],
                                   sT[c * 129 + s * 4 + 2], sT[c * 129 + s * 4 + 3]);
            *(float4*)&simbase[(size_t)gr * NN + rb + s * 4] = v;
            unsigned w = bits[(size_t)gr * NW + (rb >> 5) + (s >> 3)];
            int bo = (s & 7) * 4;
            float lm = -INFINITY;
            if ((w >> (bo + 0)) & 1) lm = fmaxf(lm, v.x);
            if ((w >> (bo + 1)) & 1) lm = fmaxf(lm, v.y);
            if ((w >> (bo + 2)) & 1) lm = fmaxf(lm, v.z);
            if ((w >> (bo + 3)) & 1) lm = fmaxf(lm, v.w);
            #pragma unroll
            for (int o = 16; o > 0; o >>= 1)
                lm = fmaxf(lm, __shfl_xor_sync(0xffffffffu, lm, o));
            if (lane == 0) atomicMax(&g_rowmax[h * NN + gr], f2ord(lm));
        }
    }
}

// ---------------- keep + exp + P@h + elu + head mean ----------------
// grid (NN/32, HH). block 256. Tile 32 rows x 64 cols.
// Thread map (R1's conflict-free layout): tx=tid&15 -> cols tx*4..+3, ty=tid>>4 -> rows ty*2+{0,1}.
#define SP_STRIDE 132
#define ATTN_SMEM ((32 * SP_STRIDE + 128 * 64 + 32 + 32) * 4)
__global__ void __launch_bounds__(256) k_attn(int step, float* __restrict__ doutp) {
    extern __shared__ float sm[];
    float* sP   = sm;                      // [32][SP_STRIDE]
    float* sHt  = sm + 32 * SP_STRIDE;     // [128][64]
    float* sRM  = sHt + 128 * 64;          // [32]
    float* sDen = sRM + 32;                // [32]

    float* out = (step == NSTEPS - 1) ? doutp : g_xbuf[step & 1];
    int h = blockIdx.y;
    int rb = blockIdx.x * 32;
    int tid = threadIdx.x;
    int warp = tid >> 5, lane = tid & 31;

    if (tid < 32) {
        sRM[tid] = ord2f(g_rowmax[h * NN + rb + tid]);
        sDen[tid] = 0.f;
    }

    int tx = tid & 15, ty = tid >> 4;      // cols tx*4+j, rows ty*2+i
    float acc[2][4];
    #pragma unroll
    for (int i = 0; i < 2; i++)
        #pragma unroll
        for (int j = 0; j < 4; j++) acc[i][j] = 0.f;

    const float* hb = g_h + (size_t)h * NN * DD;
    const float* simb = g_sim + (size_t)h * NN * NN;
    const unsigned* adjb = g_adjbits + (size_t)step * NN * NW;

    for (int cb = 0; cb < NN; cb += 128) {
        __syncthreads();
        // p-phase: warp handles one row (128 cols) per iteration; 4 iters
        #pragma unroll
        for (int t = 0; t < 4; t++) {
            int r = t * 8 + warp;
            int gr = rb + r;
            float rm = sRM[r];
            float th = 0.5f * rm;
            float4 s = *(const float4*)&simb[(size_t)gr * NN + cb + lane * 4];
            unsigned mb = adjb[(size_t)gr * NW + (cb >> 5) + (lane >> 3)];
            int b0 = (lane & 7) * 4;
            float4 p;
            p.x = (((mb >> (b0 + 0)) & 1) && s.x >= th) ? __expf(s.x - rm) : 0.f;
            p.y = (((mb >> (b0 + 1)) & 1) && s.y >= th) ? __expf(s.y - rm) : 0.f;
            p.z = (((mb >> (b0 + 2)) & 1) && s.z >= th) ? __expf(s.z - rm) : 0.f;
            p.w = (((mb >> (b0 + 3)) & 1) && s.w >= th) ? __expf(s.w - rm) : 0.f;
            *(float4*)&sP[r * SP_STRIDE + lane * 4] = p;
            float ws = p.x + p.y + p.z + p.w;
            #pragma unroll
            for (int o = 16; o > 0; o >>= 1) ws += __shfl_xor_sync(0xffffffffu, ws, o);
            if (lane == 0) sDen[r] += ws;
        }
        // h col-tile [128][64]
        #pragma unroll
        for (int t = 0; t < 8; t++) {
            int i2 = tid + t * 256;
            int cc = i2 >> 4, e = (i2 & 15) << 2;
            *(float4*)&sHt[cc * 64 + e] = *(const float4*)&hb[(size_t)(cb + cc) * DD + e];
        }
        __syncthreads();
        // GEMM: 2 rows x 4 cols per thread, k unrolled by 4 (float4 A broadcast loads)
        #pragma unroll 2
        for (int k = 0; k < 128; k += 4) {
            float4 a0 = *(const float4*)&sP[(ty * 2 + 0) * SP_STRIDE + k];
            float4 a1 = *(const float4*)&sP[(ty * 2 + 1) * SP_STRIDE + k];
            #pragma unroll
            for (int kk = 0; kk < 4; kk++) {
                float4 b = *(const float4*)&sHt[(k + kk) * 64 + tx * 4];
                float av0 = (kk == 0) ? a0.x : (kk == 1) ? a0.y : (kk == 2) ? a0.z : a0.w;
                float av1 = (kk == 0) ? a1.x : (kk == 1) ? a1.y : (kk == 2) ? a1.z : a1.w;
                acc[0][0] = fmaf(av0, b.x, acc[0][0]);
                acc[0][1] = fmaf(av0, b.y, acc[0][1]);
                acc[0][2] = fmaf(av0, b.z, acc[0][2]);
                acc[0][3] = fmaf(av0, b.w, acc[0][3]);
                acc[1][0] = fmaf(av1, b.x, acc[1][0]);
                acc[1][1] = fmaf(av1, b.y, acc[1][1]);
                acc[1][2] = fmaf(av1, b.z, acc[1][2]);
                acc[1][3] = fmaf(av1, b.w, acc[1][3]);
            }
        }
    }
    __syncthreads();

    #pragma unroll
    for (int i = 0; i < 2; i++) {
        int lr = ty * 2 + i;
        int r = rb + lr;
        float den = sDen[lr];
        float inv = (den > 0.f) ? (1.f / den) : 0.f;
        #pragma unroll
        for (int j = 0; j < 4; j++) {
            int e = tx * 4 + j;
            float v = (den > 0.f) ? (acc[i][j] * inv) : g_hmean[h * DD + e];
            v = (v > 0.f) ? v : (expf(v) - 1.f);   // elu
            atomicAdd(&out[(size_t)r * DD + e], 0.25f * v);
        }
    }
}

// ---------------- launch ----------------
extern "C" void kernel_launch(void* const* d_in, const int* in_sizes, int n_in,
                              void* d_out, int out_size) {
    const float* feat = (const float*)d_in[0];
    const int*   adj  = (const int*)d_in[1];
    const float* Ws   = (const float*)d_in[2];
    float* out = (float*)d_out;

    cudaFuncSetAttribute(k_sim,  cudaFuncAttributeMaxDynamicSharedMemorySize, SIM_SMEM);
    cudaFuncSetAttribute(k_attn, cudaFuncAttributeMaxDynamicSharedMemorySize, ATTN_SMEM);

    k_pack<<<2048, 256>>>(adj);
    for (int s = 0; s < NSTEPS; s++) {
        k_init<<<1024, 256>>>(s, out);
        k_project<<<dim3(NN / 64, HH), 256>>>(s, feat, Ws);
        k_sim<<<dim3(528, HH), 256, SIM_SMEM>>>(s);
        k_attn<<<dim3(NN / 32, HH), 256, ATTN_SMEM>>>(s, out);
    }
}

// round 14
// speedup vs baseline: 1.4960x; 1.2665x over previous
#include <cuda_runtime.h>
#include <cuda_bf16.h>
#include <math.h>
#include <cstdint>

#define NN 4096
#define DD 64
#define HH 4
#define NSTEPS 4
#define NW (NN/32)   // 128 mask words per row

// ---------------- scratch (__device__ globals; no allocations) ----------------
__device__ float          g_hn  [(size_t)HH * NN * DD];
__device__ __nv_bfloat16  g_hbhi[(size_t)HH * NN * DD];   // h bf16 hi
__device__ __nv_bfloat16  g_hblo[(size_t)HH * NN * DD];   // h bf16 lo
__device__ float          g_sim [(size_t)HH * NN * NN];   // 268 MB sim scratch
__device__ unsigned       g_rowmax[HH * NN];
__device__ float          g_hmean [HH * DD];
__device__ float          g_xbuf[2][NN * DD];
__device__ unsigned       g_adjbits[(size_t)NSTEPS * NN * NW];

__device__ __forceinline__ unsigned f2ord(float f) {
    unsigned u = __float_as_uint(f);
    return (u & 0x80000000u) ? ~u : (u | 0x80000000u);
}
__device__ __forceinline__ float ord2f(unsigned u) {
    u = (u & 0x80000000u) ? (u & 0x7FFFFFFFu) : ~u;
    return __uint_as_float(u);
}
#define ORD_NEG_INF 0x007FFFFFu

#define MMA16816(d, a, b) \
    asm volatile("mma.sync.aligned.m16n8k16.row.col.f32.bf16.bf16.f32 " \
                 "{%0,%1,%2,%3}, {%4,%5,%6,%7}, {%8,%9}, {%0,%1,%2,%3};" \
                 : "+f"((d)[0]), "+f"((d)[1]), "+f"((d)[2]), "+f"((d)[3]) \
                 : "r"((a)[0]), "r"((a)[1]), "r"((a)[2]), "r"((a)[3]), \
                   "r"((b)[0]), "r"((b)[1]))

__device__ __forceinline__ uint32_t pack_bf2(float a, float b) {
    __nv_bfloat16 ba = __float2bfloat16(a), bb = __float2bfloat16(b);
    return (uint32_t)__bfloat16_as_ushort(ba) |
           ((uint32_t)__bfloat16_as_ushort(bb) << 16);
}

// ---------------- pack adjacency bits (all steps, once) ----------------
__global__ void k_pack(const int* __restrict__ adj) {
    int lane = threadIdx.x & 31;
    size_t gw = (size_t)blockIdx.x * (blockDim.x >> 5) + (threadIdx.x >> 5);
    size_t nWtot = (size_t)NSTEPS * NN * NW;
    size_t stride = (size_t)gridDim.x * (blockDim.x >> 5);
    for (size_t w = gw; w < nWtot; w += stride) {
        int v = adj[w * 32 + lane];
        unsigned m = __ballot_sync(0xffffffffu, v > 0);
        if (lane == 0) g_adjbits[w] = m;
    }
}

// ---------------- per-step init ----------------
__global__ void k_init(int step, float* dout) {
    float* nxt = (step == NSTEPS - 1) ? dout : g_xbuf[step & 1];
    int i = blockIdx.x * blockDim.x + threadIdx.x;
    if (i < NN * DD) nxt[i] = 0.f;
    if (i < HH * NN) g_rowmax[i] = ORD_NEG_INF;
    if (i < HH * DD) g_hmean[i] = 0.f;
}

// ---------------- projection + normalize + bf16 split of h + column mean ----------------
__global__ void k_project(int step, const float* __restrict__ feat,
                          const float* __restrict__ Ws) {
    const float* x = (step == 0) ? feat : g_xbuf[(step + 1) & 1];
    int h = blockIdx.y;
    const float* W = Ws + ((size_t)step * HH + h) * DD * DD;
    int row0 = blockIdx.x * 64;

    __shared__ float sW[DD * DD];
    __shared__ float sX[64 * DD];
    __shared__ float sPart[8][16];

    for (int i = threadIdx.x; i < DD * DD; i += 256) sW[i] = W[i];
    for (int i = threadIdx.x; i < 64 * DD; i += 256) sX[i] = x[(size_t)row0 * DD + i];
    __syncthreads();

    int tx = threadIdx.x & 63;
    int ty = threadIdx.x >> 6;

    float hv[16];
    #pragma unroll
    for (int i = 0; i < 16; i++) {
        int r = ty + i * 4;
        float acc = 0.f;
        #pragma unroll
        for (int d = 0; d < DD; d++) acc = fmaf(sX[r * DD + d], sW[d * DD + tx], acc);
        hv[i] = acc;
    }

    float ss[16];
    #pragma unroll
    for (int i = 0; i < 16; i++) ss[i] = hv[i] * hv[i];
    #pragma unroll
    for (int o = 16; o > 0; o >>= 1) {
        #pragma unroll
        for (int i = 0; i < 16; i++) ss[i] += __shfl_xor_sync(0xffffffffu, ss[i], o);
    }
    int w = threadIdx.x >> 5;
    if ((threadIdx.x & 31) == 0) {
        #pragma unroll
        for (int i = 0; i < 16; i++) sPart[w][i] = ss[i];
    }
    __syncthreads();

    float msum = 0.f;
    #pragma unroll
    for (int i = 0; i < 16; i++) {
        int r = ty + i * 4;
        float nsq = sPart[ty * 2][i] + sPart[ty * 2 + 1][i];
        float rn = 1.f / (sqrtf(nsq) + 1e-12f);
        size_t idx = ((size_t)h * NN + row0 + r) * DD + tx;
        g_hn[idx] = hv[i] * rn;
        __nv_bfloat16 bh = __float2bfloat16(hv[i]);
        g_hbhi[idx] = bh;
        g_hblo[idx] = __float2bfloat16(hv[i] - __bfloat162float(bh));
        msum += hv[i];
    }
    atomicAdd(&g_hmean[h * DD + tx], msum * (1.0f / NN));
}

// ---------------- sim = hn @ hn^T / TEMP, symmetric: upper tiles only (verbatim R13) ----------------
#define SIM_SMEM (128 * 129 * 4)
__global__ void __launch_bounds__(256) k_sim(int step) {
    extern __shared__ float sm[];
    float* sA = sm;               // [64][128] k-major
    float* sB = sm + 64 * 128;    // [64][128] k-major
    int h = blockIdx.y;

    int idx = blockIdx.x, bi = 0;
    while (idx >= 32 - bi) { idx -= 32 - bi; bi++; }
    int bj = bi + idx;
    int rb = bi * 128, cb = bj * 128;

    const float* base = g_hn + (size_t)h * NN * DD;
    #pragma unroll
    for (int t = 0; t < 8; t++) {
        int i2 = threadIdx.x + t * 256;
        int r = i2 >> 4;
        int k = (i2 & 15) << 2;
        float4 va = *(const float4*)&base[(size_t)(rb + r) * DD + k];
        sA[(k + 0) * 128 + r] = va.x; sA[(k + 1) * 128 + r] = va.y;
        sA[(k + 2) * 128 + r] = va.z; sA[(k + 3) * 128 + r] = va.w;
        float4 vb = *(const float4*)&base[(size_t)(cb + r) * DD + k];
        sB[(k + 0) * 128 + r] = vb.x; sB[(k + 1) * 128 + r] = vb.y;
        sB[(k + 2) * 128 + r] = vb.z; sB[(k + 3) * 128 + r] = vb.w;
    }
    __syncthreads();

    int tx = threadIdx.x & 15, ty = threadIdx.x >> 4;
    float acc[8][8];
    #pragma unroll
    for (int i = 0; i < 8; i++)
        #pragma unroll
        for (int j = 0; j < 8; j++) acc[i][j] = 0.f;

    #pragma unroll
    for (int k = 0; k < 64; k++) {
        float4 a0 = *(const float4*)&sA[k * 128 + ty * 4];
        float4 a1 = *(const float4*)&sA[k * 128 + ty * 4 + 64];
        float4 b0 = *(const float4*)&sB[k * 128 + tx * 4];
        float4 b1 = *(const float4*)&sB[k * 128 + tx * 4 + 64];
        float a[8] = {a0.x, a0.y, a0.z, a0.w, a1.x, a1.y, a1.z, a1.w};
        float b[8] = {b0.x, b0.y, b0.z, b0.w, b1.x, b1.y, b1.z, b1.w};
        #pragma unroll
        for (int i = 0; i < 8; i++)
            #pragma unroll
            for (int j = 0; j < 8; j++) acc[i][j] = fmaf(a[i], b[j], acc[i][j]);
    }

    #pragma unroll
    for (int i = 0; i < 8; i++)
        #pragma unroll
        for (int j = 0; j < 8; j++) acc[i][j] *= 5.f;

    const unsigned* bits = g_adjbits + (size_t)step * NN * NW;
    float* simbase = g_sim + (size_t)h * NN * NN;
    int lane = threadIdx.x & 31;
    #pragma unroll
    for (int i = 0; i < 8; i++) {
        int lr = ty * 4 + (i & 3) + ((i >> 2) << 6);
        int gr = rb + lr;
        size_t o0 = (size_t)gr * NN + cb + tx * 4;
        *(float4*)&simbase[o0]      = make_float4(acc[i][0], acc[i][1], acc[i][2], acc[i][3]);
        *(float4*)&simbase[o0 + 64] = make_float4(acc[i][4], acc[i][5], acc[i][6], acc[i][7]);
        unsigned w0 = bits[(size_t)gr * NW + (cb >> 5) + (tx >> 3)];
        unsigned w1 = bits[(size_t)gr * NW + (cb >> 5) + 2 + (tx >> 3)];
        int bo = (tx & 7) * 4;
        float lm = -INFINITY;
        #pragma unroll
        for (int j = 0; j < 4; j++) {
            if ((w0 >> (bo + j)) & 1) lm = fmaxf(lm, acc[i][j]);
            if ((w1 >> (bo + j)) & 1) lm = fmaxf(lm, acc[i][4 + j]);
        }
        lm = fmaxf(lm, __shfl_xor_sync(0xffffffffu, lm, 1));
        lm = fmaxf(lm, __shfl_xor_sync(0xffffffffu, lm, 2));
        lm = fmaxf(lm, __shfl_xor_sync(0xffffffffu, lm, 4));
        lm = fmaxf(lm, __shfl_xor_sync(0xffffffffu, lm, 8));
        if ((lane & 15) == 0) atomicMax(&g_rowmax[h * NN + gr], f2ord(lm));
    }

    if (bi != bj) {
        __syncthreads();
        float* sT = sm;                  // [128][129]
        #pragma unroll
        for (int i = 0; i < 8; i++) {
            int lr = ty * 4 + (i & 3) + ((i >> 2) << 6);
            #pragma unroll
            for (int j = 0; j < 8; j++) {
                int c = tx * 4 + (j & 3) + ((j >> 2) << 6);
                sT[c * 129 + lr] = acc[i][j];
            }
        }
        __syncthreads();
        #pragma unroll
        for (int t = 0; t < 16; t++) {
            int slot = threadIdx.x + t * 256;
            int c = slot >> 5;
            int s = slot & 31;
            int gr = cb + c;
            float4 v = make_float4(sT[c * 129 + s * 4 + 0], sT[c * 129 + s * 4 + 1],
                                   sT[c * 129 + s * 4 + 2], sT[c * 129 + s * 4 + 3]);
            *(float4*)&simbase[(size_t)gr * NN + rb + s * 4] = v;
            unsigned w = bits[(size_t)gr * NW + (rb >> 5) + (s >> 3)];
            int bo = (s & 7) * 4;
            float lm = -INFINITY;
            if ((w >> (bo + 0)) & 1) lm = fmaxf(lm, v.x);
            if ((w >> (bo + 1)) & 1) lm = fmaxf(lm, v.y);
            if ((w >> (bo + 2)) & 1) lm = fmaxf(lm, v.z);
            if ((w >> (bo + 3)) & 1) lm = fmaxf(lm, v.w);
            #pragma unroll
            for (int o = 16; o > 0; o >>= 1)
                lm = fmaxf(lm, __shfl_xor_sync(0xffffffffu, lm, o));
            if (lane == 0) atomicMax(&g_rowmax[h * NN + gr], f2ord(lm));
        }
    }
}

// ---------------- keep + exp + P@h via mma.sync bf16 split + elu + head mean ----------------
// grid (NN/32, HH). block 256 (8 warps). Tile 32 rows x 64 cols, K-block 128.
// warp w: M-half mh=w&1 (16 rows), N-quarter nq=w>>1 (16 cols = 2 n-tiles of 8).
// smem (uint16 elements): sPhi[32][136], sPlo[32][136], sThi[64][138], sTlo[64][138],
//                         then fp32 sRM[32], sDen[32].
#define SPAD 136
#define TPAD 138
#define ATTN_SMEM ((32*SPAD*2 + 64*TPAD*2) * 2 + 256)
__global__ void __launch_bounds__(256) k_attn(int step, float* __restrict__ doutp) {
    extern __shared__ char smc[];
    uint16_t* sPhi = (uint16_t*)smc;
    uint16_t* sPlo = sPhi + 32 * SPAD;
    uint16_t* sThi = sPlo + 32 * SPAD;
    uint16_t* sTlo = sThi + 64 * TPAD;
    float*    sRM  = (float*)(sTlo + 64 * TPAD);
    float*    sDen = sRM + 32;

    float* out = (step == NSTEPS - 1) ? doutp : g_xbuf[step & 1];
    int h = blockIdx.y;
    int rb = blockIdx.x * 32;
    int tid = threadIdx.x;
    int warp = tid >> 5, lane = tid & 31;

    if (tid < 32) {
        sRM[tid] = ord2f(g_rowmax[h * NN + rb + tid]);
        sDen[tid] = 0.f;
    }

    const int mh = warp & 1, nq = warp >> 1;
    const int q = lane >> 2, t4 = lane & 3;

    float acc[2][4];
    #pragma unroll
    for (int i = 0; i < 2; i++)
        #pragma unroll
        for (int j = 0; j < 4; j++) acc[i][j] = 0.f;

    const __nv_bfloat16* hbh = g_hbhi + (size_t)h * NN * DD;
    const __nv_bfloat16* hbl = g_hblo + (size_t)h * NN * DD;
    const float* simb = g_sim + (size_t)h * NN * NN;
    const unsigned* adjb = g_adjbits + (size_t)step * NN * NW;

    for (int cb = 0; cb < NN; cb += 128) {
        __syncthreads();
        // ---- p-phase: warp handles one row (128 cols) per iteration; 4 iters ----
        #pragma unroll
        for (int t = 0; t < 4; t++) {
            int r = t * 8 + warp;
            int gr = rb + r;
            float rm = sRM[r];
            float th = 0.5f * rm;
            float4 s = *(const float4*)&simb[(size_t)gr * NN + cb + lane * 4];
            unsigned mb = adjb[(size_t)gr * NW + (cb >> 5) + (lane >> 3)];
            int b0 = (lane & 7) * 4;
            float4 p;
            p.x = (((mb >> (b0 + 0)) & 1) && s.x >= th) ? __expf(s.x - rm) : 0.f;
            p.y = (((mb >> (b0 + 1)) & 1) && s.y >= th) ? __expf(s.y - rm) : 0.f;
            p.z = (((mb >> (b0 + 2)) & 1) && s.z >= th) ? __expf(s.z - rm) : 0.f;
            p.w = (((mb >> (b0 + 3)) & 1) && s.w >= th) ? __expf(s.w - rm) : 0.f;
            // split into bf16 hi/lo and store
            float hx = __bfloat162float(__float2bfloat16(p.x));
            float hy = __bfloat162float(__float2bfloat16(p.y));
            float hz = __bfloat162float(__float2bfloat16(p.z));
            float hw = __bfloat162float(__float2bfloat16(p.w));
            uint2 vhi = make_uint2(pack_bf2(p.x, p.y), pack_bf2(p.z, p.w));
            uint2 vlo = make_uint2(pack_bf2(p.x - hx, p.y - hy),
                                   pack_bf2(p.z - hz, p.w - hw));
            *(uint2*)&sPhi[r * SPAD + lane * 4] = vhi;
            *(uint2*)&sPlo[r * SPAD + lane * 4] = vlo;
            float ws = p.x + p.y + p.z + p.w;
            #pragma unroll
            for (int o = 16; o > 0; o >>= 1) ws += __shfl_xor_sync(0xffffffffu, ws, o);
            if (lane == 0) sDen[r] += ws;
        }
        // ---- h col-tile transposed: sT[e][k] from g_hbhi/lo rows cb..cb+127 ----
        #pragma unroll
        for (int t = 0; t < 16; t++) {
            int i2 = tid + t * 256;         // 4096 u32 slots: 128 rows x 32
            int cc = i2 >> 5;
            int ep = (i2 & 31) * 2;
            uint32_t vh = *(const uint32_t*)&hbh[(size_t)(cb + cc) * DD + ep];
            uint32_t vl = *(const uint32_t*)&hbl[(size_t)(cb + cc) * DD + ep];
            sThi[(ep + 0) * TPAD + cc] = (uint16_t)(vh & 0xffffu);
            sThi[(ep + 1) * TPAD + cc] = (uint16_t)(vh >> 16);
            sTlo[(ep + 0) * TPAD + cc] = (uint16_t)(vl & 0xffffu);
            sTlo[(ep + 1) * TPAD + cc] = (uint16_t)(vl >> 16);
        }
        __syncthreads();
        // ---- MMA: 8 k-tiles of 16 ----
        const int ar = mh * 16 + q;
        #pragma unroll 2
        for (int kt = 0; kt < 8; kt++) {
            int k0 = kt * 16 + t4 * 2;
            uint32_t ahi[4], alo[4];
            ahi[0] = *(const uint32_t*)&sPhi[(ar + 0) * SPAD + k0];
            ahi[1] = *(const uint32_t*)&sPhi[(ar + 8) * SPAD + k0];
            ahi[2] = *(const uint32_t*)&sPhi[(ar + 0) * SPAD + k0 + 8];
            ahi[3] = *(const uint32_t*)&sPhi[(ar + 8) * SPAD + k0 + 8];
            alo[0] = *(const uint32_t*)&sPlo[(ar + 0) * SPAD + k0];
            alo[1] = *(const uint32_t*)&sPlo[(ar + 8) * SPAD + k0];
            alo[2] = *(const uint32_t*)&sPlo[(ar + 0) * SPAD + k0 + 8];
            alo[3] = *(const uint32_t*)&sPlo[(ar + 8) * SPAD + k0 + 8];
            #pragma unroll
            for (int nt = 0; nt < 2; nt++) {
                int n0 = nq * 16 + nt * 8 + q;
                uint32_t bh[2], bl[2];
                bh[0] = *(const uint32_t*)&sThi[n0 * TPAD + k0];
                bh[1] = *(const uint32_t*)&sThi[n0 * TPAD + k0 + 8];
                bl[0] = *(const uint32_t*)&sTlo[n0 * TPAD + k0];
                bl[1] = *(const uint32_t*)&sTlo[n0 * TPAD + k0 + 8];
                MMA16816(acc[nt], ahi, bh);
                MMA16816(acc[nt], ahi, bl);
                MMA16816(acc[nt], alo, bh);
            }
        }
    }
    __syncthreads();

    // ---- epilogue: normalize, fallback, elu, head-mean ----
    #pragma unroll
    for (int nt = 0; nt < 2; nt++) {
        #pragma unroll
        for (int half = 0; half < 2; half++) {
            int lr = mh * 16 + q + half * 8;
            int r = rb + lr;
            float den = sDen[lr];
            float inv = (den > 0.f) ? (1.f / den) : 0.f;
            #pragma unroll
            for (int j = 0; j < 2; j++) {
                int e = nq * 16 + nt * 8 + t4 * 2 + j;
                float a = acc[nt][half * 2 + j];
                float v = (den > 0.f) ? (a * inv) : g_hmean[h * DD + e];
                v = (v > 0.f) ? v : (expf(v) - 1.f);   // elu
                atomicAdd(&out[(size_t)r * DD + e], 0.25f * v);
            }
        }
    }
}

// ---------------- launch ----------------
extern "C" void kernel_launch(void* const* d_in, const int* in_sizes, int n_in,
                              void* d_out, int out_size) {
    const float* feat = (const float*)d_in[0];
    const int*   adj  = (const int*)d_in[1];
    const float* Ws   = (const float*)d_in[2];
    float* out = (float*)d_out;

    cudaFuncSetAttribute(k_sim,  cudaFuncAttributeMaxDynamicSharedMemorySize, SIM_SMEM);
    cudaFuncSetAttribute(k_attn, cudaFuncAttributeMaxDynamicSharedMemorySize, ATTN_SMEM);

    k_pack<<<2048, 256>>>(adj);
    for (int s = 0; s < NSTEPS; s++) {
        k_init<<<1024, 256>>>(s, out);
        k_project<<<dim3(NN / 64, HH), 256>>>(s, feat, Ws);
        k_sim<<<dim3(528, HH), 256, SIM_SMEM>>>(s);
        k_attn<<<dim3(NN / 32, HH), 256, ATTN_SMEM>>>(s, out);
    }
}

// round 15
// speedup vs baseline: 1.6117x; 1.0773x over previous
#include <cuda_runtime.h>
#include <cuda_bf16.h>
#include <math.h>
#include <cstdint>

#define NN 4096
#define DD 64
#define HH 4
#define NSTEPS 4
#define NW (NN/32)   // 128 mask words per row

// ---------------- scratch (__device__ globals; no allocations) ----------------
__device__ __nv_bfloat16  g_hnhi[(size_t)HH * NN * DD];   // normalized hn bf16 hi
__device__ __nv_bfloat16  g_hnlo[(size_t)HH * NN * DD];   // normalized hn bf16 lo
__device__ __nv_bfloat16  g_hbhi[(size_t)HH * NN * DD];   // h bf16 hi
__device__ __nv_bfloat16  g_hblo[(size_t)HH * NN * DD];   // h bf16 lo
__device__ float          g_sim [(size_t)HH * NN * NN];   // 268 MB sim scratch
__device__ unsigned       g_rowmax[HH * NN];
__device__ float          g_hmean [HH * DD];
__device__ float          g_xbuf[2][NN * DD];
__device__ unsigned       g_adjbits[(size_t)NSTEPS * NN * NW];

__device__ __forceinline__ unsigned f2ord(float f) {
    unsigned u = __float_as_uint(f);
    return (u & 0x80000000u) ? ~u : (u | 0x80000000u);
}
__device__ __forceinline__ float ord2f(unsigned u) {
    u = (u & 0x80000000u) ? (u & 0x7FFFFFFFu) : ~u;
    return __uint_as_float(u);
}
#define ORD_NEG_INF 0x007FFFFFu

#define MMA16816(d, a, b) \
    asm volatile("mma.sync.aligned.m16n8k16.row.col.f32.bf16.bf16.f32 " \
                 "{%0,%1,%2,%3}, {%4,%5,%6,%7}, {%8,%9}, {%0,%1,%2,%3};" \
                 : "+f"((d)[0]), "+f"((d)[1]), "+f"((d)[2]), "+f"((d)[3]) \
                 : "r"((a)[0]), "r"((a)[1]), "r"((a)[2]), "r"((a)[3]), \
                   "r"((b)[0]), "r"((b)[1]))

__device__ __forceinline__ uint32_t pack_bf2(float a, float b) {
    __nv_bfloat16 ba = __float2bfloat16(a), bb = __float2bfloat16(b);
    return (uint32_t)__bfloat16_as_ushort(ba) |
           ((uint32_t)__bfloat16_as_ushort(bb) << 16);
}

// ---------------- pack adjacency bits (all steps, once) ----------------
__global__ void k_pack(const int* __restrict__ adj) {
    int lane = threadIdx.x & 31;
    size_t gw = (size_t)blockIdx.x * (blockDim.x >> 5) + (threadIdx.x >> 5);
    size_t nWtot = (size_t)NSTEPS * NN * NW;
    size_t stride = (size_t)gridDim.x * (blockDim.x >> 5);
    for (size_t w = gw; w < nWtot; w += stride) {
        int v = adj[w * 32 + lane];
        unsigned m = __ballot_sync(0xffffffffu, v > 0);
        if (lane == 0) g_adjbits[w] = m;
    }
}

// ---------------- per-step init ----------------
__global__ void k_init(int step, float* dout) {
    float* nxt = (step == NSTEPS - 1) ? dout : g_xbuf[step & 1];
    int i = blockIdx.x * blockDim.x + threadIdx.x;
    if (i < NN * DD) nxt[i] = 0.f;
    if (i < HH * NN) g_rowmax[i] = ORD_NEG_INF;
    if (i < HH * DD) g_hmean[i] = 0.f;
}

// ---------------- projection + normalize + bf16 splits + column mean ----------------
__global__ void k_project(int step, const float* __restrict__ feat,
                          const float* __restrict__ Ws) {
    const float* x = (step == 0) ? feat : g_xbuf[(step + 1) & 1];
    int h = blockIdx.y;
    const float* W = Ws + ((size_t)step * HH + h) * DD * DD;
    int row0 = blockIdx.x * 64;

    __shared__ float sW[DD * DD];
    __shared__ float sX[64 * DD];
    __shared__ float sPart[8][16];

    for (int i = threadIdx.x; i < DD * DD; i += 256) sW[i] = W[i];
    for (int i = threadIdx.x; i < 64 * DD; i += 256) sX[i] = x[(size_t)row0 * DD + i];
    __syncthreads();

    int tx = threadIdx.x & 63;
    int ty = threadIdx.x >> 6;

    float hv[16];
    #pragma unroll
    for (int i = 0; i < 16; i++) {
        int r = ty + i * 4;
        float acc = 0.f;
        #pragma unroll
        for (int d = 0; d < DD; d++) acc = fmaf(sX[r * DD + d], sW[d * DD + tx], acc);
        hv[i] = acc;
    }

    float ss[16];
    #pragma unroll
    for (int i = 0; i < 16; i++) ss[i] = hv[i] * hv[i];
    #pragma unroll
    for (int o = 16; o > 0; o >>= 1) {
        #pragma unroll
        for (int i = 0; i < 16; i++) ss[i] += __shfl_xor_sync(0xffffffffu, ss[i], o);
    }
    int w = threadIdx.x >> 5;
    if ((threadIdx.x & 31) == 0) {
        #pragma unroll
        for (int i = 0; i < 16; i++) sPart[w][i] = ss[i];
    }
    __syncthreads();

    float msum = 0.f;
    #pragma unroll
    for (int i = 0; i < 16; i++) {
        int r = ty + i * 4;
        float nsq = sPart[ty * 2][i] + sPart[ty * 2 + 1][i];
        float rn = 1.f / (sqrtf(nsq) + 1e-12f);
        size_t idx = ((size_t)h * NN + row0 + r) * DD + tx;
        float hnv = hv[i] * rn;
        __nv_bfloat16 nh = __float2bfloat16(hnv);
        g_hnhi[idx] = nh;
        g_hnlo[idx] = __float2bfloat16(hnv - __bfloat162float(nh));
        __nv_bfloat16 bh = __float2bfloat16(hv[i]);
        g_hbhi[idx] = bh;
        g_hblo[idx] = __float2bfloat16(hv[i] - __bfloat162float(bh));
        msum += hv[i];
    }
    atomicAdd(&g_hmean[h * DD + tx], msum * (1.0f / NN));
}

// ---------------- sim = hn @ hn^T / TEMP via mma.sync bf16 4-term split ----------------
// grid (528, HH): upper-triangular 128x128 tile pairs. block 256 (8 warps: wm=warp&3
// rows wm*32..+31, wn=warp>>2 cols wn*64..+63). K=64, 4 k-tiles of 16.
// smem (u16): sAhi/sAlo/sBhi/sBlo [128][72]; mirror epilogue overlays fp32 sT[128][129].
#define SIMPAD 72
#define SIM_SMEM (4 * 128 * SIMPAD * 2)
__global__ void __launch_bounds__(256) k_sim(int step) {
    extern __shared__ char smc[];
    uint16_t* sAhi = (uint16_t*)smc;
    uint16_t* sAlo = sAhi + 128 * SIMPAD;
    uint16_t* sBhi = sAlo + 128 * SIMPAD;
    uint16_t* sBlo = sBhi + 128 * SIMPAD;
    int h = blockIdx.y;
    int tid = threadIdx.x;

    int idx0 = blockIdx.x, bi = 0;
    while (idx0 >= 32 - bi) { idx0 -= 32 - bi; bi++; }
    int bj = bi + idx0;
    int rb = bi * 128, cb = bj * 128;

    const __nv_bfloat16* Ah = g_hnhi + ((size_t)h * NN + rb) * DD;
    const __nv_bfloat16* Al = g_hnlo + ((size_t)h * NN + rb) * DD;
    const __nv_bfloat16* Bh = g_hnhi + ((size_t)h * NN + cb) * DD;
    const __nv_bfloat16* Bl = g_hnlo + ((size_t)h * NN + cb) * DD;
    #pragma unroll
    for (int t = 0; t < 8; t++) {
        int i2 = tid + t * 256;            // 2048 uint2 slots: 128 rows x 16
        int r = i2 >> 4, c = i2 & 15;
        size_t go = (size_t)r * DD + c * 4;
        *(uint2*)&sAhi[r * SIMPAD + c * 4] = *(const uint2*)(Ah + go);
        *(uint2*)&sAlo[r * SIMPAD + c * 4] = *(const uint2*)(Al + go);
        *(uint2*)&sBhi[r * SIMPAD + c * 4] = *(const uint2*)(Bh + go);
        *(uint2*)&sBlo[r * SIMPAD + c * 4] = *(const uint2*)(Bl + go);
    }
    __syncthreads();

    int warp = tid >> 5, lane = tid & 31;
    int wm = warp & 3, wn = warp >> 2;
    int q = lane >> 2, t4 = lane & 3;

    float d[2][8][4];
    #pragma unroll
    for (int mi = 0; mi < 2; mi++)
        #pragma unroll
        for (int nj = 0; nj < 8; nj++)
            #pragma unroll
            for (int p = 0; p < 4; p++) d[mi][nj][p] = 0.f;

    #pragma unroll
    for (int kt = 0; kt < 4; kt++) {
        int kk = kt * 16 + t4 * 2;         // u16 index into row
        uint32_t ahi[2][4], alo[2][4];
        #pragma unroll
        for (int mi = 0; mi < 2; mi++) {
            int r = wm * 32 + mi * 16 + q;
            ahi[mi][0] = *(const uint32_t*)&sAhi[(r + 0) * SIMPAD + kk];
            ahi[mi][1] = *(const uint32_t*)&sAhi[(r + 8) * SIMPAD + kk];
            ahi[mi][2] = *(const uint32_t*)&sAhi[(r + 0) * SIMPAD + kk + 8];
            ahi[mi][3] = *(const uint32_t*)&sAhi[(r + 8) * SIMPAD + kk + 8];
            alo[mi][0] = *(const uint32_t*)&sAlo[(r + 0) * SIMPAD + kk];
            alo[mi][1] = *(const uint32_t*)&sAlo[(r + 8) * SIMPAD + kk];
            alo[mi][2] = *(const uint32_t*)&sAlo[(r + 0) * SIMPAD + kk + 8];
            alo[mi][3] = *(const uint32_t*)&sAlo[(r + 8) * SIMPAD + kk + 8];
        }
        #pragma unroll
        for (int nj = 0; nj < 8; nj++) {
            int nr = wn * 64 + nj * 8 + q;
            uint32_t bh[2], bl[2];
            bh[0] = *(const uint32_t*)&sBhi[nr * SIMPAD + kk];
            bh[1] = *(const uint32_t*)&sBhi[nr * SIMPAD + kk + 8];
            bl[0] = *(const uint32_t*)&sBlo[nr * SIMPAD + kk];
            bl[1] = *(const uint32_t*)&sBlo[nr * SIMPAD + kk + 8];
            #pragma unroll
            for (int mi = 0; mi < 2; mi++) {
                MMA16816(d[mi][nj], ahi[mi], bh);
                MMA16816(d[mi][nj], ahi[mi], bl);
                MMA16816(d[mi][nj], alo[mi], bh);
                MMA16816(d[mi][nj], alo[mi], bl);
            }
        }
    }

    // scale by 1/TEMP = 5
    #pragma unroll
    for (int mi = 0; mi < 2; mi++)
        #pragma unroll
        for (int nj = 0; nj < 8; nj++)
            #pragma unroll
            for (int p = 0; p < 4; p++) d[mi][nj][p] *= 5.f;

    // row-side store + masked row max
    const unsigned* bits = g_adjbits + (size_t)step * NN * NW;
    float* simbase = g_sim + (size_t)h * NN * NN;
    int cw = (cb >> 5) + wn * 2;
    #pragma unroll
    for (int mi = 0; mi < 2; mi++) {
        #pragma unroll
        for (int half = 0; half < 2; half++) {
            int lr = wm * 32 + mi * 16 + q + half * 8;
            int gr = rb + lr;
            unsigned w0 = bits[(size_t)gr * NW + cw];
            unsigned w1 = bits[(size_t)gr * NW + cw + 1];
            float lm = -INFINITY;
            float* rowp = simbase + (size_t)gr * NN + cb + wn * 64 + t4 * 2;
            #pragma unroll
            for (int nj = 0; nj < 8; nj++) {
                float v0 = d[mi][nj][half * 2 + 0];
                float v1 = d[mi][nj][half * 2 + 1];
                *(float2*)(rowp + nj * 8) = make_float2(v0, v1);
                unsigned w = (nj < 4) ? w0 : w1;
                int bit = (nj & 3) * 8 + t4 * 2;
                if ((w >> bit) & 1)       lm = fmaxf(lm, v0);
                if ((w >> (bit + 1)) & 1) lm = fmaxf(lm, v1);
            }
            lm = fmaxf(lm, __shfl_xor_sync(0xffffffffu, lm, 1));
            lm = fmaxf(lm, __shfl_xor_sync(0xffffffffu, lm, 2));
            if (t4 == 0) atomicMax(&g_rowmax[h * NN + gr], f2ord(lm));
        }
    }

    // mirror tile: transpose via smem overlay, coalesced store + mirror row max
    if (bi != bj) {
        __syncthreads();                    // all warps done with frag smem
        float* sT = (float*)smc;            // [128][129] = 66048 B <= SIM_SMEM
        #pragma unroll
        for (int mi = 0; mi < 2; mi++)
            #pragma unroll
            for (int half = 0; half < 2; half++) {
                int lr = wm * 32 + mi * 16 + q + half * 8;
                #pragma unroll
                for (int nj = 0; nj < 8; nj++) {
                    int c = wn * 64 + nj * 8 + t4 * 2;
                    sT[(c + 0) * 129 + lr] = d[mi][nj][half * 2 + 0];
                    sT[(c + 1) * 129 + lr] = d[mi][nj][half * 2 + 1];
                }
            }
        __syncthreads();
        #pragma unroll
        for (int t = 0; t < 16; t++) {
            int slot = tid + t * 256;
            int c = slot >> 5;
            int s = slot & 31;
            int gr = cb + c;
            float4 v = make_float4(sT[c * 129 + s * 4 + 0], sT[c * 129 + s * 4 + 1],
                                   sT[c * 129 + s * 4 + 2], sT[c * 129 + s * 4 + 3]);
            *(float4*)&simbase[(size_t)gr * NN + rb + s * 4] = v;
            unsigned w = bits[(size_t)gr * NW + (rb >> 5) + (s >> 3)];
            int bo = (s & 7) * 4;
            float lm = -INFINITY;
            if ((w >> (bo + 0)) & 1) lm = fmaxf(lm, v.x);
            if ((w >> (bo + 1)) & 1) lm = fmaxf(lm, v.y);
            if ((w >> (bo + 2)) & 1) lm = fmaxf(lm, v.z);
            if ((w >> (bo + 3)) & 1) lm = fmaxf(lm, v.w);
            #pragma unroll
            for (int o = 16; o > 0; o >>= 1)
                lm = fmaxf(lm, __shfl_xor_sync(0xffffffffu, lm, o));
            if (lane == 0) atomicMax(&g_rowmax[h * NN + gr], f2ord(lm));
        }
    }
}

// ---------------- keep + exp + P@h via mma.sync bf16 4-term split ----------------
// (R14 structure + 4th MMA term for precision margin)
#define SPAD 136
#define TPAD 138
#define ATTN_SMEM ((32*SPAD*2 + 64*TPAD*2) * 2 + 256)
__global__ void __launch_bounds__(256) k_attn(int step, float* __restrict__ doutp) {
    extern __shared__ char smc[];
    uint16_t* sPhi = (uint16_t*)smc;
    uint16_t* sPlo = sPhi + 32 * SPAD;
    uint16_t* sThi = sPlo + 32 * SPAD;
    uint16_t* sTlo = sThi + 64 * TPAD;
    float*    sRM  = (float*)(sTlo + 64 * TPAD);
    float*    sDen = sRM + 32;

    float* out = (step == NSTEPS - 1) ? doutp : g_xbuf[step & 1];
    int h = blockIdx.y;
    int rb = blockIdx.x * 32;
    int tid = threadIdx.x;
    int warp = tid >> 5, lane = tid & 31;

    if (tid < 32) {
        sRM[tid] = ord2f(g_rowmax[h * NN + rb + tid]);
        sDen[tid] = 0.f;
    }

    const int mh = warp & 1, nq = warp >> 1;
    const int q = lane >> 2, t4 = lane & 3;

    float acc[2][4];
    #pragma unroll
    for (int i = 0; i < 2; i++)
        #pragma unroll
        for (int j = 0; j < 4; j++) acc[i][j] = 0.f;

    const __nv_bfloat16* hbh = g_hbhi + (size_t)h * NN * DD;
    const __nv_bfloat16* hbl = g_hblo + (size_t)h * NN * DD;
    const float* simb = g_sim + (size_t)h * NN * NN;
    const unsigned* adjb = g_adjbits + (size_t)step * NN * NW;

    for (int cb = 0; cb < NN; cb += 128) {
        __syncthreads();
        #pragma unroll
        for (int t = 0; t < 4; t++) {
            int r = t * 8 + warp;
            int gr = rb + r;
            float rm = sRM[r];
            float th = 0.5f * rm;
            float4 s = *(const float4*)&simb[(size_t)gr * NN + cb + lane * 4];
            unsigned mb = adjb[(size_t)gr * NW + (cb >> 5) + (lane >> 3)];
            int b0 = (lane & 7) * 4;
            float4 p;
            p.x = (((mb >> (b0 + 0)) & 1) && s.x >= th) ? __expf(s.x - rm) : 0.f;
            p.y = (((mb >> (b0 + 1)) & 1) && s.y >= th) ? __expf(s.y - rm) : 0.f;
            p.z = (((mb >> (b0 + 2)) & 1) && s.z >= th) ? __expf(s.z - rm) : 0.f;
            p.w = (((mb >> (b0 + 3)) & 1) && s.w >= th) ? __expf(s.w - rm) : 0.f;
            float hx = __bfloat162float(__float2bfloat16(p.x));
            float hy = __bfloat162float(__float2bfloat16(p.y));
            float hz = __bfloat162float(__float2bfloat16(p.z));
            float hw = __bfloat162float(__float2bfloat16(p.w));
            uint2 vhi = make_uint2(pack_bf2(p.x, p.y), pack_bf2(p.z, p.w));
            uint2 vlo = make_uint2(pack_bf2(p.x - hx, p.y - hy),
                                   pack_bf2(p.z - hz, p.w - hw));
            *(uint2*)&sPhi[r * SPAD + lane * 4] = vhi;
            *(uint2*)&sPlo[r * SPAD + lane * 4] = vlo;
            float ws = p.x + p.y + p.z + p.w;
            #pragma unroll
            for (int o = 16; o > 0; o >>= 1) ws += __shfl_xor_sync(0xffffffffu, ws, o);
            if (lane == 0) sDen[r] += ws;
        }
        #pragma unroll
        for (int t = 0; t < 16; t++) {
            int i2 = tid + t * 256;
            int cc = i2 >> 5;
            int ep = (i2 & 31) * 2;
            uint32_t vh = *(const uint32_t*)&hbh[(size_t)(cb + cc) * DD + ep];
            uint32_t vl = *(const uint32_t*)&hbl[(size_t)(cb + cc) * DD + ep];
            sThi[(ep + 0) * TPAD + cc] = (uint16_t)(vh & 0xffffu);
            sThi[(ep + 1) * TPAD + cc] = (uint16_t)(vh >> 16);
            sTlo[(ep + 0) * TPAD + cc] = (uint16_t)(vl & 0xffffu);
            sTlo[(ep + 1) * TPAD + cc] = (uint16_t)(vl >> 16);
        }
        __syncthreads();
        const int ar = mh * 16 + q;
        #pragma unroll 2
        for (int kt = 0; kt < 8; kt++) {
            int k0 = kt * 16 + t4 * 2;
            uint32_t ahi[4], alo[4];
            ahi[0] = *(const uint32_t*)&sPhi[(ar + 0) * SPAD + k0];
            ahi[1] = *(const uint32_t*)&sPhi[(ar + 8) * SPAD + k0];
            ahi[2] = *(const uint32_t*)&sPhi[(ar + 0) * SPAD + k0 + 8];
            ahi[3] = *(const uint32_t*)&sPhi[(ar + 8) * SPAD + k0 + 8];
            alo[0] = *(const uint32_t*)&sPlo[(ar + 0) * SPAD + k0];
            alo[1] = *(const uint32_t*)&sPlo[(ar + 8) * SPAD + k0];
            alo[2] = *(const uint32_t*)&sPlo[(ar + 0) * SPAD + k0 + 8];
            alo[3] = *(const uint32_t*)&sPlo[(ar + 8) * SPAD + k0 + 8];
            #pragma unroll
            for (int nt = 0; nt < 2; nt++) {
                int n0 = nq * 16 + nt * 8 + q;
                uint32_t bh[2], bl[2];
                bh[0] = *(const uint32_t*)&sThi[n0 * TPAD + k0];
                bh[1] = *(const uint32_t*)&sThi[n0 * TPAD + k0 + 8];
                bl[0] = *(const uint32_t*)&sTlo[n0 * TPAD + k0];
                bl[1] = *(const uint32_t*)&sTlo[n0 * TPAD + k0 + 8];
                MMA16816(acc[nt], ahi, bh);
                MMA16816(acc[nt], ahi, bl);
                MMA16816(acc[nt], alo, bh);
                MMA16816(acc[nt], alo, bl);
            }
        }
    }
    __syncthreads();

    #pragma unroll
    for (int nt = 0; nt < 2; nt++) {
        #pragma unroll
        for (int half = 0; half < 2; half++) {
            int lr = mh * 16 + q + half * 8;
            int r = rb + lr;
            float den = sDen[lr];
            float inv = (den > 0.f) ? (1.f / den) : 0.f;
            #pragma unroll
            for (int j = 0; j < 2; j++) {
                int e = nq * 16 + nt * 8 + t4 * 2 + j;
                float a = acc[nt][half * 2 + j];
                float v = (den > 0.f) ? (a * inv) : g_hmean[h * DD + e];
                v = (v > 0.f) ? v : (expf(v) - 1.f);   // elu
                atomicAdd(&out[(size_t)r * DD + e], 0.25f * v);
            }
        }
    }
}

// ---------------- launch ----------------
extern "C" void kernel_launch(void* const* d_in, const int* in_sizes, int n_in,
                              void* d_out, int out_size) {
    const float* feat = (const float*)d_in[0];
    const int*   adj  = (const int*)d_in[1];
    const float* Ws   = (const float*)d_in[2];
    float* out = (float*)d_out;

    cudaFuncSetAttribute(k_sim,  cudaFuncAttributeMaxDynamicSharedMemorySize, SIM_SMEM);
    cudaFuncSetAttribute(k_attn, cudaFuncAttributeMaxDynamicSharedMemorySize, ATTN_SMEM);

    k_pack<<<2048, 256>>>(adj);
    for (int s = 0; s < NSTEPS; s++) {
        k_init<<<1024, 256>>>(s, out);
        k_project<<<dim3(NN / 64, HH), 256>>>(s, feat, Ws);
        k_sim<<<dim3(528, HH), 256, SIM_SMEM>>>(s);
        k_attn<<<dim3(NN / 32, HH), 256, ATTN_SMEM>>>(s, out);
    }
}